// round 6
// baseline (speedup 1.0000x reference)
#include <cuda_runtime.h>
#include <cuda_fp16.h>
#include <math.h>
#include <string.h>

#define NN 50000
#define EE 800000
#define FI 32
#define TT 8
#define OO 32
#define CH 256   // FI*TT
#define SB 49    // scan blocks: ceil(50000/1024)

typedef unsigned long long u64;

// ---------------- scratch (static device globals; no allocs) ----------------
__device__ float  g_deg[NN];
__device__ float  g_dinv[NN];
__device__ int    g_cnt[NN];
__device__ int    g_cur[NN];
__device__ int    g_off[NN + 1];
__device__ int    g_bsum[SB];
__device__ int    g_bbase[SB];
__device__ int2   g_sw[EE];                 // interleaved {src, __float_as_int(norm)}
__device__ __half g_xh[(size_t)NN * CH];    // fp16 copy of X for the gather
__device__ float  g_MzT[FI * OO];           // transposed: [f][o]
__device__ float  g_MhT[FI * OO];
__device__ float  g_cbz[OO];
__device__ float  g_cbh[OO];
__device__ float  g_prob[TT];
__device__ int    g_is64;

// ---------------- packed f32x2 helpers ----------------
__device__ __forceinline__ void ffma2(u64& d, u64 a, u64 b) {
    asm("fma.rn.f32x2 %0, %1, %2, %0;" : "+l"(d) : "l"(a), "l"(b));
}
__device__ __forceinline__ u64 pack2(float x) {
    u64 r;
    unsigned u = __float_as_uint(x);
    asm("mov.b64 %0, {%1, %1};" : "=l"(r) : "r"(u));
    return r;
}
__device__ __forceinline__ void unpack2(float& lo, float& hi, u64 v) {
    unsigned a, b;
    asm("mov.b64 {%0, %1}, %2;" : "=r"(a), "=r"(b) : "l"(v));
    lo = __uint_as_float(a);
    hi = __uint_as_float(b);
}

// low-32-bit read of edge id (works for int64 little-endian and int32)
__device__ __forceinline__ int eidx(const int* __restrict__ ei32, long long idx, int is64) {
    return is64 ? ei32[2 * idx] : ei32[idx];
}

// ---------------- init (fused dtype sniffer in block 0) ----------------
__global__ void __launch_bounds__(256) k_init(const int* __restrict__ ei32) {
    int n = blockIdx.x * blockDim.x + threadIdx.x;
    if (n < NN) {
        g_deg[n] = 1.0f;   // self loop
        g_cnt[n] = 0;
    }
    if (blockIdx.x == 0) {
        __shared__ int anynz;
        if (threadIdx.x == 0) anynz = 0;
        __syncthreads();
        for (int i = threadIdx.x; i < 2048; i += 256) {
            if (ei32[2 * i + 1] != 0) anynz = 1;
        }
        __syncthreads();
        if (threadIdx.x == 0) g_is64 = anynz ? 0 : 1;
    }
}

// ---------------- X -> fp16 conversion (8 floats per thread) ----------------
__global__ void __launch_bounds__(256) k_tohalf(const float* __restrict__ X) {
    size_t i = ((size_t)blockIdx.x * blockDim.x + threadIdx.x) * 8;
    if (i >= (size_t)NN * CH) return;
    float4 a = *(const float4*)(X + i);
    float4 b = *(const float4*)(X + i + 4);
    __half2 h0 = __floats2half2_rn(a.x, a.y);
    __half2 h1 = __floats2half2_rn(a.z, a.w);
    __half2 h2 = __floats2half2_rn(b.x, b.y);
    __half2 h3 = __floats2half2_rn(b.z, b.w);
    uint4 packed;
    packed.x = *(unsigned*)&h0;
    packed.y = *(unsigned*)&h1;
    packed.z = *(unsigned*)&h2;
    packed.w = *(unsigned*)&h3;
    *(uint4*)(g_xh + i) = packed;
}

// ---------------- degree + in-degree histogram, 4 edges/thread (MLP=8) ----------------
__global__ void __launch_bounds__(256) k_hist(const int* __restrict__ ei32,
                                              const float* __restrict__ ew) {
    int base = blockIdx.x * 1024 + threadIdx.x;
    int is64 = g_is64;
    int   c[4];
    float w[4];
    #pragma unroll
    for (int k = 0; k < 4; k++) {
        int e = base + k * 256;
        if (e < EE) {
            c[k] = eidx(ei32, (long long)EE + e, is64);
            w[k] = ew[e];
        } else c[k] = -1;
    }
    #pragma unroll
    for (int k = 0; k < 4; k++) {
        if (c[k] >= 0) {
            atomicAdd(&g_deg[c[k]], w[k]);
            atomicAdd(&g_cnt[c[k]], 1);
        }
    }
}

// ---------------- scan stage 1: per-block count sums, fused dinv ----------------
__global__ void __launch_bounds__(1024) k_scan1() {
    __shared__ int wsum[32];
    int t = threadIdx.x, lane = t & 31, wid = t >> 5;
    int idx = blockIdx.x * 1024 + t;
    int v = 0;
    if (idx < NN) {
        v = g_cnt[idx];
        g_dinv[idx] = rsqrtf(g_deg[idx]);
    }
    int s = v;
    #pragma unroll
    for (int d = 16; d > 0; d >>= 1) s += __shfl_down_sync(0xFFFFFFFFu, s, d);
    if (lane == 0) wsum[wid] = s;
    __syncthreads();
    if (wid == 0) {
        int x = wsum[lane];
        #pragma unroll
        for (int d = 16; d > 0; d >>= 1) x += __shfl_down_sync(0xFFFFFFFFu, x, d);
        if (lane == 0) g_bsum[blockIdx.x] = x;
    }
}

// ---------------- scan stage 2: exclusive scan of SB block sums ----------------
__global__ void __launch_bounds__(32) k_scan2() {
    if (threadIdx.x == 0) {
        int acc = 0;
        for (int b = 0; b < SB; b++) {
            g_bbase[b] = acc;
            acc += g_bsum[b];
        }
    }
}

// ---------------- scan stage 3: per-node offsets; g_cur seeded = g_off ----------------
__global__ void __launch_bounds__(1024) k_scan3() {
    __shared__ int wsum[32];
    int t = threadIdx.x, lane = t & 31, wid = t >> 5;
    int idx = blockIdx.x * 1024 + t;
    int v = (idx < NN) ? g_cnt[idx] : 0;
    int inc = v;
    #pragma unroll
    for (int d = 1; d < 32; d <<= 1) {
        int x = __shfl_up_sync(0xFFFFFFFFu, inc, d);
        if (lane >= d) inc += x;
    }
    if (lane == 31) wsum[wid] = inc;
    __syncthreads();
    if (wid == 0) {
        int w = wsum[lane];
        #pragma unroll
        for (int d = 1; d < 32; d <<= 1) {
            int x = __shfl_up_sync(0xFFFFFFFFu, w, d);
            if (lane >= d) w += x;
        }
        wsum[lane] = w;
    }
    __syncthreads();
    int warpoff = (wid > 0) ? wsum[wid - 1] : 0;
    int excl = g_bbase[blockIdx.x] + warpoff + (inc - v);
    if (idx < NN) {
        g_off[idx] = excl;
        g_cur[idx] = excl;
    }
    if (idx == NN - 1) g_off[NN] = EE;
}

// ---------------- CSR fill, 4 edges/thread (MLP high) ----------------
__global__ void __launch_bounds__(256) k_fill(const int* __restrict__ ei32,
                                              const float* __restrict__ ew) {
    int base = blockIdx.x * 1024 + threadIdx.x;
    int is64 = g_is64;
    int   r[4], c[4];
    float w[4];
    #pragma unroll
    for (int k = 0; k < 4; k++) {
        int e = base + k * 256;
        if (e < EE) {
            r[k] = eidx(ei32, e, is64);
            c[k] = eidx(ei32, (long long)EE + e, is64);
            w[k] = ew[e];
        } else c[k] = -1;
    }
    float dr[4], dc[4];
    #pragma unroll
    for (int k = 0; k < 4; k++) {
        if (c[k] >= 0) { dr[k] = g_dinv[r[k]]; dc[k] = g_dinv[c[k]]; }
    }
    #pragma unroll
    for (int k = 0; k < 4; k++) {
        if (c[k] >= 0) {
            float nrm = dr[k] * w[k] * dc[k];
            int idx = atomicAdd(&g_cur[c[k]], 1);
            g_sw[idx] = make_int2(r[k], __float_as_int(nrm));
        }
    }
}

// ---------------- prep: MzT = (Lz[:, :32] @ Wz)^T etc., biases, softmax ----------------
__global__ void __launch_bounds__(1024) k_prep(
        const float* __restrict__ Wz, const float* __restrict__ bz,
        const float* __restrict__ Wh, const float* __restrict__ bh,
        const float* __restrict__ Lz, const float* __restrict__ lzb,
        const float* __restrict__ Lh, const float* __restrict__ lhb,
        const float* __restrict__ attn) {
    int t = threadIdx.x;
    int o = t >> 5, f = t & 31;
    float mz = 0.f, mh = 0.f;
    #pragma unroll
    for (int k = 0; k < 32; k++) {
        mz += Lz[o * 64 + k] * Wz[k * 32 + f];
        mh += Lh[o * 64 + k] * Wh[k * 32 + f];
    }
    g_MzT[f * 32 + o] = mz;   // transposed store
    g_MhT[f * 32 + o] = mh;
    if (f == 0) {
        float cz = lzb[o], chh = lhb[o];
        for (int k = 0; k < 32; k++) {
            cz  += Lz[o * 64 + k] * bz[k];
            chh += Lh[o * 64 + k] * bh[k];
        }
        g_cbz[o] = cz;
        g_cbh[o] = chh;
    }
    if (t == 0) {
        float m = -1e30f;
        for (int i = 0; i < TT; i++) m = fmaxf(m, attn[i]);
        float e[TT], s = 0.f;
        for (int i = 0; i < TT; i++) { e[i] = __expf(attn[i] - m); s += e[i]; }
        float inv = 1.0f / s;
        for (int i = 0; i < TT; i++) g_prob[i] = e[i] * inv;
    }
}

// ---------------- single-edge gather helper ----------------
__device__ __forceinline__ void edge_fma(int2 e, int lane,
        float& a0, float& a1, float& a2, float& a3,
        float& a4, float& a5, float& a6, float& a7) {
    float wt = __int_as_float(e.y);
    uint4 p = *(const uint4*)(g_xh + (size_t)e.x * CH + lane * 8);
    float2 f0 = __half22float2(*(__half2*)&p.x);
    float2 f1 = __half22float2(*(__half2*)&p.y);
    float2 f2 = __half22float2(*(__half2*)&p.z);
    float2 f3 = __half22float2(*(__half2*)&p.w);
    a0 = fmaf(wt, f0.x, a0); a1 = fmaf(wt, f0.y, a1);
    a2 = fmaf(wt, f1.x, a2); a3 = fmaf(wt, f1.y, a3);
    a4 = fmaf(wt, f2.x, a4); a5 = fmaf(wt, f2.y, a5);
    a6 = fmaf(wt, f3.x, a6); a7 = fmaf(wt, f3.y, a7);
}

// ---------------- fused: 8-deep fp16 gather + packed-f32x2 epilogue ----------------
__global__ void __launch_bounds__(256) k_fused(const float* __restrict__ X,
                                               float* __restrict__ out) {
    __shared__ float MzT[FI * OO];
    __shared__ float MhT[FI * OO];
    __shared__ float cbz_s[OO], cbh_s[OO], pr_s[TT];
    __shared__ float xs[8][CH];

    int t = threadIdx.x;
    for (int i = t; i < FI * OO; i += 256) {
        MzT[i] = g_MzT[i];
        MhT[i] = g_MhT[i];
    }
    if (t < OO) { cbz_s[t] = g_cbz[t]; cbh_s[t] = g_cbh[t]; }
    if (t < TT) pr_s[t] = g_prob[t];
    __syncthreads();

    int w = t >> 5, lane = t & 31;
    int n = blockIdx.x * 8 + w;          // grid = 6250 -> exactly 50000

    // ---- self-loop term from fp32 X (channels lane*8 .. lane*8+7) ----
    float dv = g_dinv[n];
    float sn = dv * dv;
    const float4* xn = (const float4*)(X + (size_t)n * CH);
    float4 a = xn[2 * lane];
    float4 b = xn[2 * lane + 1];
    float acc0 = sn * a.x, acc1 = sn * a.y, acc2 = sn * a.z, acc3 = sn * a.w;
    float acc4 = sn * b.x, acc5 = sn * b.y, acc6 = sn * b.z, acc7 = sn * b.w;

    // ---- fp16 gather, unrolled x8 for MLP ----
    int j = g_off[n], end = g_off[n + 1];
    for (; j + 8 <= end; j += 8) {
        int2 e[8];
        #pragma unroll
        for (int k = 0; k < 8; k++) e[k] = g_sw[j + k];
        uint4 p[8];
        #pragma unroll
        for (int k = 0; k < 8; k++)
            p[k] = *(const uint4*)(g_xh + (size_t)e[k].x * CH + lane * 8);
        #pragma unroll
        for (int k = 0; k < 8; k++) {
            float wt = __int_as_float(e[k].y);
            float2 f0 = __half22float2(*(__half2*)&p[k].x);
            float2 f1 = __half22float2(*(__half2*)&p[k].y);
            float2 f2 = __half22float2(*(__half2*)&p[k].z);
            float2 f3 = __half22float2(*(__half2*)&p[k].w);
            acc0 = fmaf(wt, f0.x, acc0); acc1 = fmaf(wt, f0.y, acc1);
            acc2 = fmaf(wt, f1.x, acc2); acc3 = fmaf(wt, f1.y, acc3);
            acc4 = fmaf(wt, f2.x, acc4); acc5 = fmaf(wt, f2.y, acc5);
            acc6 = fmaf(wt, f3.x, acc6); acc7 = fmaf(wt, f3.y, acc7);
        }
    }
    for (; j < end; j++) {
        int2 e = g_sw[j];
        edge_fma(e, lane, acc0, acc1, acc2, acc3, acc4, acc5, acc6, acc7);
    }

    // ---- stage x into shared (channel layout f*8 + t) ----
    *(float4*)&xs[w][lane * 8]     = make_float4(acc0, acc1, acc2, acc3);
    *(float4*)&xs[w][lane * 8 + 4] = make_float4(acc4, acc5, acc6, acc7);
    __syncwarp();

    // ---- epilogue: packed f32x2, t-pairs; lane = output o ----
    u64 az2[4], ah2[4];
    u64 cz2 = pack2(cbz_s[lane]);
    u64 ch2 = pack2(cbh_s[lane]);
    #pragma unroll
    for (int k = 0; k < 4; k++) { az2[k] = cz2; ah2[k] = ch2; }

    #pragma unroll
    for (int f = 0; f < FI; f++) {
        float4 q0 = *(const float4*)&xs[w][f * 8];
        float4 q1 = *(const float4*)&xs[w][f * 8 + 4];
        u64 qq0, qq1, qq2, qq3;
        memcpy(&qq0, &q0.x, 8);
        memcpy(&qq1, &q0.z, 8);
        memcpy(&qq2, &q1.x, 8);
        memcpy(&qq3, &q1.z, 8);
        u64 m1 = pack2(MzT[f * 32 + lane]);
        u64 m2 = pack2(MhT[f * 32 + lane]);
        ffma2(az2[0], m1, qq0); ffma2(az2[1], m1, qq1);
        ffma2(az2[2], m1, qq2); ffma2(az2[3], m1, qq3);
        ffma2(ah2[0], m2, qq0); ffma2(ah2[1], m2, qq1);
        ffma2(ah2[2], m2, qq2); ffma2(ah2[3], m2, qq3);
    }

    float az[TT], ah[TT];
    #pragma unroll
    for (int k = 0; k < 4; k++) {
        unpack2(az[2 * k], az[2 * k + 1], az2[k]);
        unpack2(ah[2 * k], ah[2 * k + 1], ah2[k]);
    }

    float acc = 0.f;
    #pragma unroll
    for (int tt = 0; tt < TT; tt++) {
        float z = 1.0f / (1.0f + __expf(-az[tt]));
        float h = tanhf(ah[tt]);
        acc = fmaf(pr_s[tt] * (1.0f - z), h, acc);
    }
    out[(size_t)n * OO + lane] = acc;
}

// ---------------- launch ----------------
extern "C" void kernel_launch(void* const* d_in, const int* in_sizes, int n_in,
                              void* d_out, int out_size) {
    const float* X    = (const float*)d_in[0];
    const int*   EI   = (const int*)d_in[1];
    const float* EW   = (const float*)d_in[2];
    const float* Wz   = (const float*)d_in[3];
    const float* bz   = (const float*)d_in[4];
    // d_in[5], d_in[6] (Wr, br): dead — R gate multiplies H == 0
    const float* Wh   = (const float*)d_in[7];
    const float* bh   = (const float*)d_in[8];
    const float* Lz   = (const float*)d_in[9];
    const float* lzb  = (const float*)d_in[10];
    // d_in[11], d_in[12] (Lr, lr_b): dead
    const float* Lh   = (const float*)d_in[13];
    const float* lhb  = (const float*)d_in[14];
    const float* attn = (const float*)d_in[15];
    float* out = (float*)d_out;

    int egrid = (EE + 1023) / 1024;
    k_init<<<(NN + 255) / 256, 256>>>(EI);
    k_tohalf<<<(int)(((size_t)NN * CH / 8 + 255) / 256), 256>>>(X);
    k_hist<<<egrid, 256>>>(EI, EW);
    k_scan1<<<SB, 1024>>>();
    k_scan2<<<1, 32>>>();
    k_scan3<<<SB, 1024>>>();
    k_prep<<<1, 1024>>>(Wz, bz, Wh, bh, Lz, lzb, Lh, lhb, attn);
    k_fill<<<egrid, 256>>>(EI, EW);
    k_fused<<<NN / 8, 256>>>(X, out);
}

// round 7
// speedup vs baseline: 1.0107x; 1.0107x over previous
#include <cuda_runtime.h>
#include <cuda_fp16.h>
#include <math.h>
#include <string.h>

#define NN 50000
#define EE 800000
#define FI 32
#define TT 8
#define OO 32
#define CH 256   // FI*TT
#define SB 49    // scan blocks: ceil(50000/1024)

typedef unsigned long long u64;

// ---------------- scratch (static device globals; no allocs) ----------------
__device__ float  g_deg[NN];
__device__ float  g_dinv[NN];
__device__ int    g_cnt[NN];
__device__ int    g_cur[NN];
__device__ int    g_off[NN + 1];
__device__ int    g_bsum[SB];
__device__ int    g_bbase[SB];
__device__ int2   g_sw[EE];                 // interleaved {src, __float_as_int(norm)}
__device__ __half g_xh[(size_t)NN * CH];    // fp16 copy of X for the gather
__device__ float  g_MzT[FI * OO];           // transposed: [f][o]
__device__ float  g_MhT[FI * OO];
__device__ float  g_cbz[OO];
__device__ float  g_cbh[OO];
__device__ float  g_prob[TT];
__device__ int    g_is64;

// ---------------- packed f32x2 helpers ----------------
__device__ __forceinline__ void ffma2(u64& d, u64 a, u64 b) {
    asm("fma.rn.f32x2 %0, %1, %2, %0;" : "+l"(d) : "l"(a), "l"(b));
}
__device__ __forceinline__ u64 pack2(float x) {
    u64 r;
    unsigned u = __float_as_uint(x);
    asm("mov.b64 %0, {%1, %1};" : "=l"(r) : "r"(u));
    return r;
}
__device__ __forceinline__ void unpack2(float& lo, float& hi, u64 v) {
    unsigned a, b;
    asm("mov.b64 {%0, %1}, %2;" : "=r"(a), "=r"(b) : "l"(v));
    lo = __uint_as_float(a);
    hi = __uint_as_float(b);
}

// low-32-bit read of edge id (works for int64 little-endian and int32)
__device__ __forceinline__ int eidx(const int* __restrict__ ei32, long long idx, int is64) {
    return is64 ? ei32[2 * idx] : ei32[idx];
}

// ---------------- init (fused dtype sniffer in block 0) ----------------
__global__ void __launch_bounds__(256) k_init(const int* __restrict__ ei32) {
    int n = blockIdx.x * blockDim.x + threadIdx.x;
    if (n < NN) {
        g_deg[n] = 1.0f;   // self loop
        g_cnt[n] = 0;
    }
    if (blockIdx.x == 0) {
        __shared__ int anynz;
        if (threadIdx.x == 0) anynz = 0;
        __syncthreads();
        for (int i = threadIdx.x; i < 2048; i += 256) {
            if (ei32[2 * i + 1] != 0) anynz = 1;
        }
        __syncthreads();
        if (threadIdx.x == 0) g_is64 = anynz ? 0 : 1;
    }
}

// ---------------- X -> fp16 conversion (8 floats per thread) ----------------
__global__ void __launch_bounds__(256) k_tohalf(const float* __restrict__ X) {
    size_t i = ((size_t)blockIdx.x * blockDim.x + threadIdx.x) * 8;
    if (i >= (size_t)NN * CH) return;
    float4 a = *(const float4*)(X + i);
    float4 b = *(const float4*)(X + i + 4);
    __half2 h0 = __floats2half2_rn(a.x, a.y);
    __half2 h1 = __floats2half2_rn(a.z, a.w);
    __half2 h2 = __floats2half2_rn(b.x, b.y);
    __half2 h3 = __floats2half2_rn(b.z, b.w);
    uint4 packed;
    packed.x = *(unsigned*)&h0;
    packed.y = *(unsigned*)&h1;
    packed.z = *(unsigned*)&h2;
    packed.w = *(unsigned*)&h3;
    *(uint4*)(g_xh + i) = packed;
}

// ---------------- degree + in-degree histogram, 4 edges/thread (MLP=8) ----------------
__global__ void __launch_bounds__(256) k_hist(const int* __restrict__ ei32,
                                              const float* __restrict__ ew) {
    int base = blockIdx.x * 1024 + threadIdx.x;
    int is64 = g_is64;
    int   c[4];
    float w[4];
    #pragma unroll
    for (int k = 0; k < 4; k++) {
        int e = base + k * 256;
        if (e < EE) {
            c[k] = eidx(ei32, (long long)EE + e, is64);
            w[k] = ew[e];
        } else c[k] = -1;
    }
    #pragma unroll
    for (int k = 0; k < 4; k++) {
        if (c[k] >= 0) {
            atomicAdd(&g_deg[c[k]], w[k]);
            atomicAdd(&g_cnt[c[k]], 1);
        }
    }
}

// ---------------- scan stage 1: per-block count sums, fused dinv ----------------
__global__ void __launch_bounds__(1024) k_scan1() {
    __shared__ int wsum[32];
    int t = threadIdx.x, lane = t & 31, wid = t >> 5;
    int idx = blockIdx.x * 1024 + t;
    int v = 0;
    if (idx < NN) {
        v = g_cnt[idx];
        g_dinv[idx] = rsqrtf(g_deg[idx]);
    }
    int s = v;
    #pragma unroll
    for (int d = 16; d > 0; d >>= 1) s += __shfl_down_sync(0xFFFFFFFFu, s, d);
    if (lane == 0) wsum[wid] = s;
    __syncthreads();
    if (wid == 0) {
        int x = wsum[lane];
        #pragma unroll
        for (int d = 16; d > 0; d >>= 1) x += __shfl_down_sync(0xFFFFFFFFu, x, d);
        if (lane == 0) g_bsum[blockIdx.x] = x;
    }
}

// ---------------- scan stage 2: exclusive scan of SB block sums ----------------
__global__ void __launch_bounds__(32) k_scan2() {
    if (threadIdx.x == 0) {
        int acc = 0;
        for (int b = 0; b < SB; b++) {
            g_bbase[b] = acc;
            acc += g_bsum[b];
        }
    }
}

// ---------------- scan stage 3: per-node offsets; g_cur seeded = g_off ----------------
__global__ void __launch_bounds__(1024) k_scan3() {
    __shared__ int wsum[32];
    int t = threadIdx.x, lane = t & 31, wid = t >> 5;
    int idx = blockIdx.x * 1024 + t;
    int v = (idx < NN) ? g_cnt[idx] : 0;
    int inc = v;
    #pragma unroll
    for (int d = 1; d < 32; d <<= 1) {
        int x = __shfl_up_sync(0xFFFFFFFFu, inc, d);
        if (lane >= d) inc += x;
    }
    if (lane == 31) wsum[wid] = inc;
    __syncthreads();
    if (wid == 0) {
        int w = wsum[lane];
        #pragma unroll
        for (int d = 1; d < 32; d <<= 1) {
            int x = __shfl_up_sync(0xFFFFFFFFu, w, d);
            if (lane >= d) w += x;
        }
        wsum[lane] = w;
    }
    __syncthreads();
    int warpoff = (wid > 0) ? wsum[wid - 1] : 0;
    int excl = g_bbase[blockIdx.x] + warpoff + (inc - v);
    if (idx < NN) {
        g_off[idx] = excl;
        g_cur[idx] = excl;
    }
    if (idx == NN - 1) g_off[NN] = EE;
}

// ---------------- CSR fill, 4 edges/thread (MLP high) ----------------
__global__ void __launch_bounds__(256) k_fill(const int* __restrict__ ei32,
                                              const float* __restrict__ ew) {
    int base = blockIdx.x * 1024 + threadIdx.x;
    int is64 = g_is64;
    int   r[4], c[4];
    float w[4];
    #pragma unroll
    for (int k = 0; k < 4; k++) {
        int e = base + k * 256;
        if (e < EE) {
            r[k] = eidx(ei32, e, is64);
            c[k] = eidx(ei32, (long long)EE + e, is64);
            w[k] = ew[e];
        } else c[k] = -1;
    }
    float dr[4], dc[4];
    #pragma unroll
    for (int k = 0; k < 4; k++) {
        if (c[k] >= 0) { dr[k] = g_dinv[r[k]]; dc[k] = g_dinv[c[k]]; }
    }
    #pragma unroll
    for (int k = 0; k < 4; k++) {
        if (c[k] >= 0) {
            float nrm = dr[k] * w[k] * dc[k];
            int idx = atomicAdd(&g_cur[c[k]], 1);
            g_sw[idx] = make_int2(r[k], __float_as_int(nrm));
        }
    }
}

// ---------------- prep: MzT = (Lz[:, :32] @ Wz)^T etc., biases, softmax ----------------
__global__ void __launch_bounds__(1024) k_prep(
        const float* __restrict__ Wz, const float* __restrict__ bz,
        const float* __restrict__ Wh, const float* __restrict__ bh,
        const float* __restrict__ Lz, const float* __restrict__ lzb,
        const float* __restrict__ Lh, const float* __restrict__ lhb,
        const float* __restrict__ attn) {
    int t = threadIdx.x;
    int o = t >> 5, f = t & 31;
    float mz = 0.f, mh = 0.f;
    #pragma unroll
    for (int k = 0; k < 32; k++) {
        mz += Lz[o * 64 + k] * Wz[k * 32 + f];
        mh += Lh[o * 64 + k] * Wh[k * 32 + f];
    }
    g_MzT[f * 32 + o] = mz;   // transposed store
    g_MhT[f * 32 + o] = mh;
    if (f == 0) {
        float cz = lzb[o], chh = lhb[o];
        for (int k = 0; k < 32; k++) {
            cz  += Lz[o * 64 + k] * bz[k];
            chh += Lh[o * 64 + k] * bh[k];
        }
        g_cbz[o] = cz;
        g_cbh[o] = chh;
    }
    if (t == 0) {
        float m = -1e30f;
        for (int i = 0; i < TT; i++) m = fmaxf(m, attn[i]);
        float e[TT], s = 0.f;
        for (int i = 0; i < TT; i++) { e[i] = __expf(attn[i] - m); s += e[i]; }
        float inv = 1.0f / s;
        for (int i = 0; i < TT; i++) g_prob[i] = e[i] * inv;
    }
}

// ---------------- single-edge gather helper ----------------
__device__ __forceinline__ void edge_fma(int2 e, int lane,
        float& a0, float& a1, float& a2, float& a3,
        float& a4, float& a5, float& a6, float& a7) {
    float wt = __int_as_float(e.y);
    uint4 p = *(const uint4*)(g_xh + (size_t)e.x * CH + lane * 8);
    float2 f0 = __half22float2(*(__half2*)&p.x);
    float2 f1 = __half22float2(*(__half2*)&p.y);
    float2 f2 = __half22float2(*(__half2*)&p.z);
    float2 f3 = __half22float2(*(__half2*)&p.w);
    a0 = fmaf(wt, f0.x, a0); a1 = fmaf(wt, f0.y, a1);
    a2 = fmaf(wt, f1.x, a2); a3 = fmaf(wt, f1.y, a3);
    a4 = fmaf(wt, f2.x, a4); a5 = fmaf(wt, f2.y, a5);
    a6 = fmaf(wt, f3.x, a6); a7 = fmaf(wt, f3.y, a7);
}

// ---------------- fused: x4-unrolled fp16 gather + packed-f32x2 epilogue ----------------
__global__ void __launch_bounds__(256) k_fused(const float* __restrict__ X,
                                               float* __restrict__ out) {
    __shared__ float MzT[FI * OO];
    __shared__ float MhT[FI * OO];
    __shared__ float cbz_s[OO], cbh_s[OO], pr_s[TT];
    __shared__ float xs[8][CH];

    int t = threadIdx.x;
    for (int i = t; i < FI * OO; i += 256) {
        MzT[i] = g_MzT[i];
        MhT[i] = g_MhT[i];
    }
    if (t < OO) { cbz_s[t] = g_cbz[t]; cbh_s[t] = g_cbh[t]; }
    if (t < TT) pr_s[t] = g_prob[t];
    __syncthreads();

    int w = t >> 5, lane = t & 31;
    int n = blockIdx.x * 8 + w;          // grid = 6250 -> exactly 50000

    // ---- self-loop term from fp32 X (channels lane*8 .. lane*8+7) ----
    float dv = g_dinv[n];
    float sn = dv * dv;
    const float4* xn = (const float4*)(X + (size_t)n * CH);
    float4 a = xn[2 * lane];
    float4 b = xn[2 * lane + 1];
    float acc0 = sn * a.x, acc1 = sn * a.y, acc2 = sn * a.z, acc3 = sn * a.w;
    float acc4 = sn * b.x, acc5 = sn * b.y, acc6 = sn * b.z, acc7 = sn * b.w;

    // ---- fp16 gather, unrolled x4 for MLP ----
    int j = g_off[n], end = g_off[n + 1];
    int rem = (end - j) & 3;
    for (int k = 0; k < rem; k++, j++) {
        int2 e = g_sw[j];
        edge_fma(e, lane, acc0, acc1, acc2, acc3, acc4, acc5, acc6, acc7);
    }
    for (; j < end; j += 4) {
        int2 e0 = g_sw[j];
        int2 e1 = g_sw[j + 1];
        int2 e2 = g_sw[j + 2];
        int2 e3 = g_sw[j + 3];
        uint4 p0 = *(const uint4*)(g_xh + (size_t)e0.x * CH + lane * 8);
        uint4 p1 = *(const uint4*)(g_xh + (size_t)e1.x * CH + lane * 8);
        uint4 p2 = *(const uint4*)(g_xh + (size_t)e2.x * CH + lane * 8);
        uint4 p3 = *(const uint4*)(g_xh + (size_t)e3.x * CH + lane * 8);
        {
            float wt = __int_as_float(e0.y);
            float2 f0 = __half22float2(*(__half2*)&p0.x);
            float2 f1 = __half22float2(*(__half2*)&p0.y);
            float2 f2 = __half22float2(*(__half2*)&p0.z);
            float2 f3 = __half22float2(*(__half2*)&p0.w);
            acc0 = fmaf(wt, f0.x, acc0); acc1 = fmaf(wt, f0.y, acc1);
            acc2 = fmaf(wt, f1.x, acc2); acc3 = fmaf(wt, f1.y, acc3);
            acc4 = fmaf(wt, f2.x, acc4); acc5 = fmaf(wt, f2.y, acc5);
            acc6 = fmaf(wt, f3.x, acc6); acc7 = fmaf(wt, f3.y, acc7);
        }
        {
            float wt = __int_as_float(e1.y);
            float2 f0 = __half22float2(*(__half2*)&p1.x);
            float2 f1 = __half22float2(*(__half2*)&p1.y);
            float2 f2 = __half22float2(*(__half2*)&p1.z);
            float2 f3 = __half22float2(*(__half2*)&p1.w);
            acc0 = fmaf(wt, f0.x, acc0); acc1 = fmaf(wt, f0.y, acc1);
            acc2 = fmaf(wt, f1.x, acc2); acc3 = fmaf(wt, f1.y, acc3);
            acc4 = fmaf(wt, f2.x, acc4); acc5 = fmaf(wt, f2.y, acc5);
            acc6 = fmaf(wt, f3.x, acc6); acc7 = fmaf(wt, f3.y, acc7);
        }
        {
            float wt = __int_as_float(e2.y);
            float2 f0 = __half22float2(*(__half2*)&p2.x);
            float2 f1 = __half22float2(*(__half2*)&p2.y);
            float2 f2 = __half22float2(*(__half2*)&p2.z);
            float2 f3 = __half22float2(*(__half2*)&p2.w);
            acc0 = fmaf(wt, f0.x, acc0); acc1 = fmaf(wt, f0.y, acc1);
            acc2 = fmaf(wt, f1.x, acc2); acc3 = fmaf(wt, f1.y, acc3);
            acc4 = fmaf(wt, f2.x, acc4); acc5 = fmaf(wt, f2.y, acc5);
            acc6 = fmaf(wt, f3.x, acc6); acc7 = fmaf(wt, f3.y, acc7);
        }
        {
            float wt = __int_as_float(e3.y);
            float2 f0 = __half22float2(*(__half2*)&p3.x);
            float2 f1 = __half22float2(*(__half2*)&p3.y);
            float2 f2 = __half22float2(*(__half2*)&p3.z);
            float2 f3 = __half22float2(*(__half2*)&p3.w);
            acc0 = fmaf(wt, f0.x, acc0); acc1 = fmaf(wt, f0.y, acc1);
            acc2 = fmaf(wt, f1.x, acc2); acc3 = fmaf(wt, f1.y, acc3);
            acc4 = fmaf(wt, f2.x, acc4); acc5 = fmaf(wt, f2.y, acc5);
            acc6 = fmaf(wt, f3.x, acc6); acc7 = fmaf(wt, f3.y, acc7);
        }
    }

    // ---- stage x into shared (channel layout f*8 + t) ----
    *(float4*)&xs[w][lane * 8]     = make_float4(acc0, acc1, acc2, acc3);
    *(float4*)&xs[w][lane * 8 + 4] = make_float4(acc4, acc5, acc6, acc7);
    __syncwarp();

    // ---- epilogue: packed f32x2, t-pairs; lane = output o ----
    u64 az2[4], ah2[4];
    u64 cz2 = pack2(cbz_s[lane]);
    u64 ch2 = pack2(cbh_s[lane]);
    #pragma unroll
    for (int k = 0; k < 4; k++) { az2[k] = cz2; ah2[k] = ch2; }

    #pragma unroll
    for (int f = 0; f < FI; f++) {
        float4 q0 = *(const float4*)&xs[w][f * 8];
        float4 q1 = *(const float4*)&xs[w][f * 8 + 4];
        u64 qq0, qq1, qq2, qq3;
        memcpy(&qq0, &q0.x, 8);
        memcpy(&qq1, &q0.z, 8);
        memcpy(&qq2, &q1.x, 8);
        memcpy(&qq3, &q1.z, 8);
        u64 m1 = pack2(MzT[f * 32 + lane]);
        u64 m2 = pack2(MhT[f * 32 + lane]);
        ffma2(az2[0], m1, qq0); ffma2(az2[1], m1, qq1);
        ffma2(az2[2], m1, qq2); ffma2(az2[3], m1, qq3);
        ffma2(ah2[0], m2, qq0); ffma2(ah2[1], m2, qq1);
        ffma2(ah2[2], m2, qq2); ffma2(ah2[3], m2, qq3);
    }

    float az[TT], ah[TT];
    #pragma unroll
    for (int k = 0; k < 4; k++) {
        unpack2(az[2 * k], az[2 * k + 1], az2[k]);
        unpack2(ah[2 * k], ah[2 * k + 1], ah2[k]);
    }

    float acc = 0.f;
    #pragma unroll
    for (int tt = 0; tt < TT; tt++) {
        float z = 1.0f / (1.0f + __expf(-az[tt]));
        float h = tanhf(ah[tt]);
        acc = fmaf(pr_s[tt] * (1.0f - z), h, acc);
    }
    out[(size_t)n * OO + lane] = acc;
}

// ---------------- launch ----------------
extern "C" void kernel_launch(void* const* d_in, const int* in_sizes, int n_in,
                              void* d_out, int out_size) {
    const float* X    = (const float*)d_in[0];
    const int*   EI   = (const int*)d_in[1];
    const float* EW   = (const float*)d_in[2];
    const float* Wz   = (const float*)d_in[3];
    const float* bz   = (const float*)d_in[4];
    // d_in[5], d_in[6] (Wr, br): dead — R gate multiplies H == 0
    const float* Wh   = (const float*)d_in[7];
    const float* bh   = (const float*)d_in[8];
    const float* Lz   = (const float*)d_in[9];
    const float* lzb  = (const float*)d_in[10];
    // d_in[11], d_in[12] (Lr, lr_b): dead
    const float* Lh   = (const float*)d_in[13];
    const float* lhb  = (const float*)d_in[14];
    const float* attn = (const float*)d_in[15];
    float* out = (float*)d_out;

    int egrid = (EE + 1023) / 1024;
    k_init<<<(NN + 255) / 256, 256>>>(EI);
    k_tohalf<<<(int)(((size_t)NN * CH / 8 + 255) / 256), 256>>>(X);
    k_hist<<<egrid, 256>>>(EI, EW);
    k_scan1<<<SB, 1024>>>();
    k_scan2<<<1, 32>>>();
    k_scan3<<<SB, 1024>>>();
    k_prep<<<1, 1024>>>(Wz, bz, Wh, bh, Lz, lzb, Lh, lhb, attn);
    k_fill<<<egrid, 256>>>(EI, EW);
    k_fused<<<NN / 8, 256>>>(X, out);
}

// round 9
// speedup vs baseline: 1.0729x; 1.0616x over previous
#include <cuda_runtime.h>
#include <cuda_fp16.h>
#include <math.h>
#include <string.h>

#define NN 50000
#define EE 800000
#define FI 32
#define TT 8
#define OO 32
#define CH 256   // FI*TT
#define SB 49    // scan blocks: ceil(50000/1024)
#define FIXS 16777216.0f          // 2^24 fixed-point scale for edge weights
#define FIXMASK ((1ull << 40) - 1ull)

typedef unsigned long long u64;

// ---------------- scratch (static device globals; no allocs) ----------------
__device__ u64    g_pack[NN];               // (count << 40) | fixedpoint(sum ew)
__device__ float  g_dinv[NN];
__device__ int    g_off[NN + 1];
__device__ int    g_bsum[SB];
__device__ int4   g_rcwe[EE];               // {row, col, rank, __float_as_int(ew)}
__device__ int2   g_sw[EE];                 // CSR: {src, __float_as_int(norm)}
__device__ __half g_xh[(size_t)NN * CH];    // fp16 copy of X for the gather
__device__ float  g_MzT[FI * OO];           // transposed: [f][o]
__device__ float  g_MhT[FI * OO];
__device__ float  g_cbz[OO];
__device__ float  g_cbh[OO];
__device__ float  g_prob[TT];
__device__ int    g_is64;

// ---------------- packed f32x2 helpers ----------------
__device__ __forceinline__ void ffma2(u64& d, u64 a, u64 b) {
    asm("fma.rn.f32x2 %0, %1, %2, %0;" : "+l"(d) : "l"(a), "l"(b));
}
__device__ __forceinline__ u64 pack2(float x) {
    u64 r;
    unsigned u = __float_as_uint(x);
    asm("mov.b64 %0, {%1, %1};" : "=l"(r) : "r"(u));
    return r;
}
__device__ __forceinline__ void unpack2(float& lo, float& hi, u64 v) {
    unsigned a, b;
    asm("mov.b64 {%0, %1}, %2;" : "=r"(a), "=r"(b) : "l"(v));
    lo = __uint_as_float(a);
    hi = __uint_as_float(b);
}

// low-32-bit read of edge id (works for int64 little-endian and int32)
__device__ __forceinline__ int eidx(const int* __restrict__ ei32, long long idx, int is64) {
    return is64 ? ei32[2 * idx] : ei32[idx];
}

// ---------------- tohalf + pack-init + dtype sniffer ----------------
// grid covers NN*CH/8 = 1.6M threads (6250 blocks x 256)
__global__ void __launch_bounds__(256) k_tohalf(const float* __restrict__ X,
                                                const int* __restrict__ ei32) {
    size_t tid = (size_t)blockIdx.x * blockDim.x + threadIdx.x;
    size_t i = tid * 8;
    if (i < (size_t)NN * CH) {
        float4 a = *(const float4*)(X + i);
        float4 b = *(const float4*)(X + i + 4);
        __half2 h0 = __floats2half2_rn(a.x, a.y);
        __half2 h1 = __floats2half2_rn(a.z, a.w);
        __half2 h2 = __floats2half2_rn(b.x, b.y);
        __half2 h3 = __floats2half2_rn(b.z, b.w);
        uint4 packed;
        packed.x = *(unsigned*)&h0;
        packed.y = *(unsigned*)&h1;
        packed.z = *(unsigned*)&h2;
        packed.w = *(unsigned*)&h3;
        *(uint4*)(g_xh + i) = packed;
    }
    if (tid < NN) g_pack[tid] = (u64)1 << 24;   // self-loop: deg = 1.0 fixed-point, count 0
    if (blockIdx.x == 0) {
        __shared__ int anynz;
        if (threadIdx.x == 0) anynz = 0;
        __syncthreads();
        for (int k = threadIdx.x; k < 2048; k += 256) {
            if (ei32[2 * k + 1] != 0) anynz = 1;
        }
        __syncthreads();
        if (threadIdx.x == 0) g_is64 = anynz ? 0 : 1;
    }
}

// ---------------- hist: ONE 64-bit atomic per edge; rank from return value ----------------
__global__ void __launch_bounds__(256) k_hist(const int* __restrict__ ei32,
                                              const float* __restrict__ ew) {
    int e = blockIdx.x * blockDim.x + threadIdx.x;
    if (e >= EE) return;
    int is64 = g_is64;
    int r = eidx(ei32, e, is64);
    int c = eidx(ei32, (long long)EE + e, is64);
    float w = ew[e];
    u64 add = ((u64)1 << 40) | (u64)__float2uint_rn(w * FIXS);
    u64 old = atomicAdd(&g_pack[c], add);
    int rank = (int)(old >> 40);
    g_rcwe[e] = make_int4(r, c, rank, __float_as_int(w));
}

// ---------------- scan stage 1: per-block count sums, fused dinv ----------------
__global__ void __launch_bounds__(1024) k_scan1() {
    __shared__ int wsum[32];
    int t = threadIdx.x, lane = t & 31, wid = t >> 5;
    int idx = blockIdx.x * 1024 + t;
    int v = 0;
    if (idx < NN) {
        u64 p = g_pack[idx];
        v = (int)(p >> 40);
        float deg = (float)(p & FIXMASK) * (1.0f / FIXS);
        g_dinv[idx] = rsqrtf(deg);
    }
    int s = v;
    #pragma unroll
    for (int d = 16; d > 0; d >>= 1) s += __shfl_down_sync(0xFFFFFFFFu, s, d);
    if (lane == 0) wsum[wid] = s;
    __syncthreads();
    if (wid == 0) {
        int x = wsum[lane];
        #pragma unroll
        for (int d = 16; d > 0; d >>= 1) x += __shfl_down_sync(0xFFFFFFFFu, x, d);
        if (lane == 0) g_bsum[blockIdx.x] = x;
    }
}

// ---------------- scan stage 2+3 merged: per-node exclusive offsets ----------------
__global__ void __launch_bounds__(1024) k_scan3() {
    __shared__ int wsum[32];
    __shared__ int base_s;
    int t = threadIdx.x, lane = t & 31, wid = t >> 5;

    // warp 0: sum of g_bsum[0 .. blockIdx.x)
    if (wid == 0) {
        int acc = 0;
        for (int i = lane; i < blockIdx.x; i += 32) acc += g_bsum[i];
        #pragma unroll
        for (int d = 16; d > 0; d >>= 1) acc += __shfl_down_sync(0xFFFFFFFFu, acc, d);
        if (lane == 0) base_s = acc;
    }

    int idx = blockIdx.x * 1024 + t;
    int v = 0;
    if (idx < NN) v = (int)(g_pack[idx] >> 40);
    int inc = v;
    #pragma unroll
    for (int d = 1; d < 32; d <<= 1) {
        int x = __shfl_up_sync(0xFFFFFFFFu, inc, d);
        if (lane >= d) inc += x;
    }
    if (lane == 31) wsum[wid] = inc;
    __syncthreads();
    if (wid == 0) {
        int w = wsum[lane];
        #pragma unroll
        for (int d = 1; d < 32; d <<= 1) {
            int x = __shfl_up_sync(0xFFFFFFFFu, w, d);
            if (lane >= d) w += x;
        }
        wsum[lane] = w;
    }
    __syncthreads();
    int warpoff = (wid > 0) ? wsum[wid - 1] : 0;
    int excl = base_s + warpoff + (inc - v);
    if (idx < NN) g_off[idx] = excl;
    if (idx == NN - 1) g_off[NN] = EE;
}

// ---------------- CSR fill: atomic-free (idx = off[col] + rank) ----------------
__global__ void __launch_bounds__(256) k_fill() {
    int e = blockIdx.x * blockDim.x + threadIdx.x;
    if (e >= EE) return;
    int4 q = g_rcwe[e];
    float nrm = g_dinv[q.x] * __int_as_float(q.w) * g_dinv[q.y];
    g_sw[g_off[q.y] + q.z] = make_int2(q.x, __float_as_int(nrm));
}

// ---------------- prep: MzT = (Lz[:, :32] @ Wz)^T etc., biases, softmax ----------------
__global__ void __launch_bounds__(1024) k_prep(
        const float* __restrict__ Wz, const float* __restrict__ bz,
        const float* __restrict__ Wh, const float* __restrict__ bh,
        const float* __restrict__ Lz, const float* __restrict__ lzb,
        const float* __restrict__ Lh, const float* __restrict__ lhb,
        const float* __restrict__ attn) {
    int t = threadIdx.x;
    int o = t >> 5, f = t & 31;
    float mz = 0.f, mh = 0.f;
    #pragma unroll
    for (int k = 0; k < 32; k++) {
        mz += Lz[o * 64 + k] * Wz[k * 32 + f];
        mh += Lh[o * 64 + k] * Wh[k * 32 + f];
    }
    g_MzT[f * 32 + o] = mz;   // transposed store
    g_MhT[f * 32 + o] = mh;
    if (f == 0) {
        float cz = lzb[o], chh = lhb[o];
        for (int k = 0; k < 32; k++) {
            cz  += Lz[o * 64 + k] * bz[k];
            chh += Lh[o * 64 + k] * bh[k];
        }
        g_cbz[o] = cz;
        g_cbh[o] = chh;
    }
    if (t == 0) {
        float m = -1e30f;
        for (int i = 0; i < TT; i++) m = fmaxf(m, attn[i]);
        float e[TT], s = 0.f;
        for (int i = 0; i < TT; i++) { e[i] = __expf(attn[i] - m); s += e[i]; }
        float inv = 1.0f / s;
        for (int i = 0; i < TT; i++) g_prob[i] = e[i] * inv;
    }
}

// ---------------- single-edge gather helper ----------------
__device__ __forceinline__ void edge_fma(int2 e, int lane,
        float& a0, float& a1, float& a2, float& a3,
        float& a4, float& a5, float& a6, float& a7) {
    float wt = __int_as_float(e.y);
    uint4 p = *(const uint4*)(g_xh + (size_t)e.x * CH + lane * 8);
    float2 f0 = __half22float2(*(__half2*)&p.x);
    float2 f1 = __half22float2(*(__half2*)&p.y);
    float2 f2 = __half22float2(*(__half2*)&p.z);
    float2 f3 = __half22float2(*(__half2*)&p.w);
    a0 = fmaf(wt, f0.x, a0); a1 = fmaf(wt, f0.y, a1);
    a2 = fmaf(wt, f1.x, a2); a3 = fmaf(wt, f1.y, a3);
    a4 = fmaf(wt, f2.x, a4); a5 = fmaf(wt, f2.y, a5);
    a6 = fmaf(wt, f3.x, a6); a7 = fmaf(wt, f3.y, a7);
}

// ---------------- fused: x4-unrolled fp16 gather + packed-f32x2 epilogue ----------------
__global__ void __launch_bounds__(256, 4) k_fused(float* __restrict__ out) {
    __shared__ float MzT[FI * OO];
    __shared__ float MhT[FI * OO];
    __shared__ float cbz_s[OO], cbh_s[OO], pr_s[TT];
    __shared__ float xs[8][CH];

    int t = threadIdx.x;
    for (int i = t; i < FI * OO; i += 256) {
        MzT[i] = g_MzT[i];
        MhT[i] = g_MhT[i];
    }
    if (t < OO) { cbz_s[t] = g_cbz[t]; cbh_s[t] = g_cbh[t]; }
    if (t < TT) pr_s[t] = g_prob[t];
    __syncthreads();

    int w = t >> 5, lane = t & 31;
    int n = blockIdx.x * 8 + w;          // grid = 6250 -> exactly 50000

    // ---- self-loop term from fp16 g_xh (L2-hot; channels lane*8 .. lane*8+7) ----
    float dv = g_dinv[n];
    float sn = dv * dv;
    uint4 ps = *(const uint4*)(g_xh + (size_t)n * CH + lane * 8);
    float2 s0 = __half22float2(*(__half2*)&ps.x);
    float2 s1 = __half22float2(*(__half2*)&ps.y);
    float2 s2 = __half22float2(*(__half2*)&ps.z);
    float2 s3 = __half22float2(*(__half2*)&ps.w);
    float acc0 = sn * s0.x, acc1 = sn * s0.y, acc2 = sn * s1.x, acc3 = sn * s1.y;
    float acc4 = sn * s2.x, acc5 = sn * s2.y, acc6 = sn * s3.x, acc7 = sn * s3.y;

    // ---- fp16 gather, unrolled x4 for MLP ----
    int j = g_off[n], end = g_off[n + 1];
    int rem = (end - j) & 3;
    for (int k = 0; k < rem; k++, j++) {
        int2 e = g_sw[j];
        edge_fma(e, lane, acc0, acc1, acc2, acc3, acc4, acc5, acc6, acc7);
    }
    for (; j < end; j += 4) {
        int2 e0 = g_sw[j];
        int2 e1 = g_sw[j + 1];
        int2 e2 = g_sw[j + 2];
        int2 e3 = g_sw[j + 3];
        uint4 p0 = *(const uint4*)(g_xh + (size_t)e0.x * CH + lane * 8);
        uint4 p1 = *(const uint4*)(g_xh + (size_t)e1.x * CH + lane * 8);
        uint4 p2 = *(const uint4*)(g_xh + (size_t)e2.x * CH + lane * 8);
        uint4 p3 = *(const uint4*)(g_xh + (size_t)e3.x * CH + lane * 8);
        {
            float wt = __int_as_float(e0.y);
            float2 f0 = __half22float2(*(__half2*)&p0.x);
            float2 f1 = __half22float2(*(__half2*)&p0.y);
            float2 f2 = __half22float2(*(__half2*)&p0.z);
            float2 f3 = __half22float2(*(__half2*)&p0.w);
            acc0 = fmaf(wt, f0.x, acc0); acc1 = fmaf(wt, f0.y, acc1);
            acc2 = fmaf(wt, f1.x, acc2); acc3 = fmaf(wt, f1.y, acc3);
            acc4 = fmaf(wt, f2.x, acc4); acc5 = fmaf(wt, f2.y, acc5);
            acc6 = fmaf(wt, f3.x, acc6); acc7 = fmaf(wt, f3.y, acc7);
        }
        {
            float wt = __int_as_float(e1.y);
            float2 f0 = __half22float2(*(__half2*)&p1.x);
            float2 f1 = __half22float2(*(__half2*)&p1.y);
            float2 f2 = __half22float2(*(__half2*)&p1.z);
            float2 f3 = __half22float2(*(__half2*)&p1.w);
            acc0 = fmaf(wt, f0.x, acc0); acc1 = fmaf(wt, f0.y, acc1);
            acc2 = fmaf(wt, f1.x, acc2); acc3 = fmaf(wt, f1.y, acc3);
            acc4 = fmaf(wt, f2.x, acc4); acc5 = fmaf(wt, f2.y, acc5);
            acc6 = fmaf(wt, f3.x, acc6); acc7 = fmaf(wt, f3.y, acc7);
        }
        {
            float wt = __int_as_float(e2.y);
            float2 f0 = __half22float2(*(__half2*)&p2.x);
            float2 f1 = __half22float2(*(__half2*)&p2.y);
            float2 f2 = __half22float2(*(__half2*)&p2.z);
            float2 f3 = __half22float2(*(__half2*)&p2.w);
            acc0 = fmaf(wt, f0.x, acc0); acc1 = fmaf(wt, f0.y, acc1);
            acc2 = fmaf(wt, f1.x, acc2); acc3 = fmaf(wt, f1.y, acc3);
            acc4 = fmaf(wt, f2.x, acc4); acc5 = fmaf(wt, f2.y, acc5);
            acc6 = fmaf(wt, f3.x, acc6); acc7 = fmaf(wt, f3.y, acc7);
        }
        {
            float wt = __int_as_float(e3.y);
            float2 f0 = __half22float2(*(__half2*)&p3.x);
            float2 f1 = __half22float2(*(__half2*)&p3.y);
            float2 f2 = __half22float2(*(__half2*)&p3.z);
            float2 f3 = __half22float2(*(__half2*)&p3.w);
            acc0 = fmaf(wt, f0.x, acc0); acc1 = fmaf(wt, f0.y, acc1);
            acc2 = fmaf(wt, f1.x, acc2); acc3 = fmaf(wt, f1.y, acc3);
            acc4 = fmaf(wt, f2.x, acc4); acc5 = fmaf(wt, f2.y, acc5);
            acc6 = fmaf(wt, f3.x, acc6); acc7 = fmaf(wt, f3.y, acc7);
        }
    }

    // ---- stage x into shared (channel layout f*8 + t) ----
    *(float4*)&xs[w][lane * 8]     = make_float4(acc0, acc1, acc2, acc3);
    *(float4*)&xs[w][lane * 8 + 4] = make_float4(acc4, acc5, acc6, acc7);
    __syncwarp();

    // ---- epilogue: packed f32x2, t-pairs; lane = output o ----
    u64 az2[4], ah2[4];
    u64 cz2 = pack2(cbz_s[lane]);
    u64 ch2 = pack2(cbh_s[lane]);
    #pragma unroll
    for (int k = 0; k < 4; k++) { az2[k] = cz2; ah2[k] = ch2; }

    #pragma unroll
    for (int f = 0; f < FI; f++) {
        float4 q0 = *(const float4*)&xs[w][f * 8];
        float4 q1 = *(const float4*)&xs[w][f * 8 + 4];
        u64 qq0, qq1, qq2, qq3;
        memcpy(&qq0, &q0.x, 8);
        memcpy(&qq1, &q0.z, 8);
        memcpy(&qq2, &q1.x, 8);
        memcpy(&qq3, &q1.z, 8);
        u64 m1 = pack2(MzT[f * 32 + lane]);
        u64 m2 = pack2(MhT[f * 32 + lane]);
        ffma2(az2[0], m1, qq0); ffma2(az2[1], m1, qq1);
        ffma2(az2[2], m1, qq2); ffma2(az2[3], m1, qq3);
        ffma2(ah2[0], m2, qq0); ffma2(ah2[1], m2, qq1);
        ffma2(ah2[2], m2, qq2); ffma2(ah2[3], m2, qq3);
    }

    float az[TT], ah[TT];
    #pragma unroll
    for (int k = 0; k < 4; k++) {
        unpack2(az[2 * k], az[2 * k + 1], az2[k]);
        unpack2(ah[2 * k], ah[2 * k + 1], ah2[k]);
    }

    float acc = 0.f;
    #pragma unroll
    for (int tt = 0; tt < TT; tt++) {
        float z = 1.0f / (1.0f + __expf(-az[tt]));
        float h = tanhf(ah[tt]);
        acc = fmaf(pr_s[tt] * (1.0f - z), h, acc);
    }
    out[(size_t)n * OO + lane] = acc;
}

// ---------------- launch ----------------
extern "C" void kernel_launch(void* const* d_in, const int* in_sizes, int n_in,
                              void* d_out, int out_size) {
    const float* X    = (const float*)d_in[0];
    const int*   EI   = (const int*)d_in[1];
    const float* EW   = (const float*)d_in[2];
    const float* Wz   = (const float*)d_in[3];
    const float* bz   = (const float*)d_in[4];
    // d_in[5], d_in[6] (Wr, br): dead — R gate multiplies H == 0
    const float* Wh   = (const float*)d_in[7];
    const float* bh   = (const float*)d_in[8];
    const float* Lz   = (const float*)d_in[9];
    const float* lzb  = (const float*)d_in[10];
    // d_in[11], d_in[12] (Lr, lr_b): dead
    const float* Lh   = (const float*)d_in[13];
    const float* lhb  = (const float*)d_in[14];
    const float* attn = (const float*)d_in[15];
    float* out = (float*)d_out;

    k_tohalf<<<(int)(((size_t)NN * CH / 8 + 255) / 256), 256>>>(X, EI);
    k_hist<<<(EE + 255) / 256, 256>>>(EI, EW);
    k_scan1<<<SB, 1024>>>();
    k_scan3<<<SB, 1024>>>();
    k_prep<<<1, 1024>>>(Wz, bz, Wh, bh, Lz, lzb, Lh, lhb, attn);
    k_fill<<<(EE + 255) / 256, 256>>>();
    k_fused<<<NN / 8, 256>>>(out);
}